// round 16
// baseline (speedup 1.0000x reference)
#include <cuda_runtime.h>
#include <cuda_fp16.h>
#include <math.h>

#define N_NODES 50000
#define NSTR    (N_NODES + 1)   // feature-row stride; row N_NODES = reserved zero row
#define N_EDGES 800000
#define E_TOT   850000          // edges + self loops
#define NE4     (N_EDGES / 4)   // 200000
#define U       64
#define NG      512
#define F_IN    9
#define SCAN_B  1024
#define SCAN_NB ((N_NODES + SCAN_B - 1) / SCAN_B)   // 49
#define NTILES  ((N_NODES + 15) / 16)               // 3125
#define FULL    0xffffffffu

// ---------------- scratch (device globals; zero-initialized at load) --------
__device__ uint2  g_bufA[2 * NSTR * 16];      // fp16 features*dinv; row N_NODES stays 0
__device__ uint2  g_bufB[2 * NSTR * 16];
__device__ float4 g_xpack[2 * N_NODES * 2];   // 32B/node: [as_f32, x0..x8 f16, pad]
__device__ float  g_ad[2 * N_NODES];
__device__ float  g_dinv[2 * N_NODES];
__device__ int    g_deg[2 * N_NODES];         // real-edge count; re-zeroed by k_scan3
__device__ int    g_rowtmp[2 * N_NODES];
__device__ int    g_rowptr[2 * (N_NODES + 1)];
__device__ int    g_bsum[2 * SCAN_NB];
__device__ int    g_eoff[2 * N_EDGES];        // per-edge within-dst ordinal
__device__ int    g_csrc[2 * E_TOT];          // src per CSR slot
__device__ float  g_wa[F_IN], g_wd[F_IN];
__device__ float  g_psum[2 * NG];             // re-zeroed by k_final each pass
__device__ float  g_pcnt[2 * NG];

// fast tanh: ~7 SASS inst; rel err ~1e-6
__device__ __forceinline__ float ftanh(float x) {
    float e = __expf(2.f * x);
    return 1.f - __fdividef(2.f, e + 1.f);
}

// ---------------- CSR build ----------------
// k_deg: histogram + record each edge's within-dst ordinal; block0 computes wa/wd
__global__ void k_deg(const int* __restrict__ ei_a, const int* __restrict__ ei_b,
                      const float* __restrict__ W, const float* __restrict__ a_src,
                      const float* __restrict__ a_dst) {
    if (blockIdx.x == 0 && blockIdx.y == 0) {
        int t = threadIdx.x;
        if (t < F_IN) {
            float s = 0.f;
            for (int c = 0; c < U; c++) s += W[t * U + c] * a_src[c];
            g_wa[t] = s;
        } else if (t >= 16 && t < 16 + F_IN) {
            int f = t - 16;
            float s = 0.f;
            for (int c = 0; c < U; c++) s += W[f * U + c] * a_dst[c];
            g_wd[f] = s;
        }
    }
    int br = blockIdx.y;
    int i = blockIdx.x * blockDim.x + threadIdx.x;
    if (i >= NE4) return;
    const int4* dst4 = reinterpret_cast<const int4*>((br ? ei_b : ei_a) + N_EDGES);
    int4 d = dst4[i];
    int* deg = g_deg + br * N_NODES;
    int4 o;
    o.x = atomicAdd(&deg[d.x], 1);
    o.y = atomicAdd(&deg[d.y], 1);
    o.z = atomicAdd(&deg[d.z], 1);
    o.w = atomicAdd(&deg[d.w], 1);
    reinterpret_cast<int4*>(g_eoff + br * N_EDGES)[i] = o;
}
__global__ void k_scan1() {
    __shared__ int sm[SCAN_B];
    int br = blockIdx.y;
    int t = threadIdx.x;
    int i = blockIdx.x * SCAN_B + t;
    int v = (i < N_NODES) ? (g_deg[br * N_NODES + i] + 1) : 0;   // +1 self loop
    sm[t] = v;
    __syncthreads();
#pragma unroll
    for (int off = 1; off < SCAN_B; off <<= 1) {
        int add = (t >= off) ? sm[t - off] : 0;
        __syncthreads();
        sm[t] += add;
        __syncthreads();
    }
    if (i < N_NODES) g_rowtmp[br * N_NODES + i] = sm[t];
    if (t == SCAN_B - 1) g_bsum[br * SCAN_NB + blockIdx.x] = sm[t];
}
// scan3: finalize CSR + dinv + 32B packed [as_f32, x f16]; re-zero deg
__global__ void k_scan3(const float* __restrict__ xa, const float* __restrict__ xb) {
    __shared__ int bsm[SCAN_NB];
    int br = blockIdx.y;
    int t = threadIdx.x;
    if (t < SCAN_NB) bsm[t] = g_bsum[br * SCAN_NB + t];
    __syncthreads();
    int i = blockIdx.x * blockDim.x + t;
    if (i >= N_NODES) return;
    int blk = i / SCAN_B;
    int pre = 0;
    for (int b = 0; b < blk; b++) pre += bsm[b];
    int incl = g_rowtmp[br * N_NODES + i] + pre;
    int d = g_deg[br * N_NODES + i] + 1;       // + self loop
    g_deg[br * N_NODES + i] = 0;               // restore zero for next replay
    g_rowptr[br * (N_NODES + 1) + i + 1] = incl;
    g_dinv[br * N_NODES + i] = rsqrtf((float)d);
    if (i == 0) g_rowptr[br * (N_NODES + 1)] = 0;
    const float* x = br ? xb : xa;
    const float* xi = x + i * F_IN;
    float v[F_IN];
    float as = 0.f, ad = 0.f;
#pragma unroll
    for (int f = 0; f < F_IN; f++) {
        v[f] = xi[f];
        as += v[f] * g_wa[f];
        ad += v[f] * g_wd[f];
    }
    g_ad[br * N_NODES + i] = ad;
    __half2 h01 = __floats2half2_rn(v[0], v[1]);
    __half2 h23 = __floats2half2_rn(v[2], v[3]);
    __half2 h45 = __floats2half2_rn(v[4], v[5]);
    __half2 h67 = __floats2half2_rn(v[6], v[7]);
    __half2 h8z = __floats2half2_rn(v[8], 0.f);
    float4* xp = g_xpack + ((size_t)br * N_NODES + i) * 2;
    float4 q0, q1;
    q0.x = as;
    q0.y = __uint_as_float(*(unsigned*)&h01);
    q0.z = __uint_as_float(*(unsigned*)&h23);
    q0.w = __uint_as_float(*(unsigned*)&h45);
    q1.x = __uint_as_float(*(unsigned*)&h67);
    q1.y = __uint_as_float(*(unsigned*)&h8z);
    q1.z = 0.f; q1.w = 0.f;
    xp[0] = q0;
    xp[1] = q1;
}
// fill: atomic-free. pos = rowptr[dst] + recorded ordinal; self loop -> last slot
__global__ void k_fill(const int* __restrict__ ei_a, const int* __restrict__ ei_b) {
    int br = blockIdx.y;
    int i = blockIdx.x * blockDim.x + threadIdx.x;
    const int* rp = g_rowptr + br * (N_NODES + 1);
    int* cs = g_csrc + br * E_TOT;
    if (i < NE4) {
        const int* ei = br ? ei_b : ei_a;
        int4 s = reinterpret_cast<const int4*>(ei)[i];
        int4 d = reinterpret_cast<const int4*>(ei + N_EDGES)[i];
        int4 o = reinterpret_cast<const int4*>(g_eoff + br * N_EDGES)[i];
        cs[rp[d.x] + o.x] = s.x;
        cs[rp[d.y] + o.y] = s.y;
        cs[rp[d.z] + o.z] = s.z;
        cs[rp[d.w] + o.w] = s.w;
    } else {
        int n = i - NE4;                       // self loops: one per node
        if (n < N_NODES) cs[rp[n + 1] - 1] = n;
    }
}

// ---------------- GAT: softmax aggregate of 32B packed x, then @W -----------
__global__ void k_gat_gather(const float* __restrict__ W, const float* __restrict__ b) {
    __shared__ float Ws[F_IN * U];
    __shared__ float bs[U];
    int tid = threadIdx.x;
    for (int i = tid; i < F_IN * U; i += blockDim.x) Ws[i] = W[i];
    if (tid < U) bs[tid] = b[tid];
    __syncthreads();
    int br = blockIdx.y;
    int lane = tid & 31;
    int node = blockIdx.x * (blockDim.x >> 5) + (tid >> 5);
    if (node >= N_NODES) return;
    const int*    cs = g_csrc + br * E_TOT;
    const int*    rp = g_rowptr + br * (N_NODES + 1);
    const float4* xp = g_xpack + (size_t)br * N_NODES * 2;
    int k0 = rp[node], k1 = rp[node + 1];
    float ad_n = g_ad[br * N_NODES + node];
    float acc[F_IN] = {0, 0, 0, 0, 0, 0, 0, 0, 0};
    float ssum = 0.f;
    for (int k = k0 + lane; k < k1; k += 32) {
        int s = cs[k];
        float4 q0 = xp[s * 2];
        float4 q1 = xp[s * 2 + 1];
        float e = q0.x + ad_n;
        e = e > 0.f ? e : 0.2f * e;
        e = fminf(e, 80.f);
        float ex = __expf(e);
        ssum += ex;
        unsigned u01 = __float_as_uint(q0.y), u23 = __float_as_uint(q0.z);
        unsigned u45 = __float_as_uint(q0.w), u67 = __float_as_uint(q1.x);
        unsigned u8z = __float_as_uint(q1.y);
        float2 x01 = __half22float2(*(__half2*)&u01);
        float2 x23 = __half22float2(*(__half2*)&u23);
        float2 x45 = __half22float2(*(__half2*)&u45);
        float2 x67 = __half22float2(*(__half2*)&u67);
        float2 x8z = __half22float2(*(__half2*)&u8z);
        acc[0] += ex * x01.x; acc[1] += ex * x01.y;
        acc[2] += ex * x23.x; acc[3] += ex * x23.y;
        acc[4] += ex * x45.x; acc[5] += ex * x45.y;
        acc[6] += ex * x67.x; acc[7] += ex * x67.y;
        acc[8] += ex * x8z.x;
    }
#pragma unroll
    for (int o = 16; o > 0; o >>= 1) {
        ssum += __shfl_xor_sync(FULL, ssum, o);
#pragma unroll
        for (int f = 0; f < F_IN; f++) acc[f] += __shfl_xor_sync(FULL, acc[f], o);
    }
    float inv = 1.f / ssum;
    int c0 = 2 * lane;
    float y0 = bs[c0], y1 = bs[c0 + 1];
#pragma unroll
    for (int f = 0; f < F_IN; f++) {
        float v = acc[f] * inv;
        y0 += v * Ws[f * U + c0];
        y1 += v * Ws[f * U + c0 + 1];
    }
    float dn = g_dinv[br * N_NODES + node];   // pre-scale for GCN1's gather
    __half2* out2 = reinterpret_cast<__half2*>(g_bufA) + ((size_t)br * NSTR + node) * 32;
    out2[lane] = __floats2half2_rn(ftanh(y0) * dn, ftanh(y1) * dn);
}

// GEMV via smem-broadcast x (16B-aligned stage; offsets 0/68 floats bank-free)
#define STAGE_F 136
__device__ __forceinline__ void gemv64(const float4* __restrict__ Wsm,
                                       float* stage, int half_off, int sub,
                                       float v0, float v1, float v2, float v3,
                                       float& y0, float& y1, float& y2, float& y3) {
    *reinterpret_cast<float4*>(stage + half_off + sub * 4) = make_float4(v0, v1, v2, v3);
    __syncwarp();
    const float* xs = stage + half_off;
#pragma unroll 4
    for (int q = 0; q < 16; q++) {
        float4 xv = *reinterpret_cast<const float4*>(xs + q * 4);
        float4 w0 = Wsm[(4 * q + 0) * 16 + sub];
        float4 w1 = Wsm[(4 * q + 1) * 16 + sub];
        float4 w2 = Wsm[(4 * q + 2) * 16 + sub];
        float4 w3 = Wsm[(4 * q + 3) * 16 + sub];
        y0 += xv.x * w0.x + xv.y * w1.x + xv.z * w2.x + xv.w * w3.x;
        y1 += xv.x * w0.y + xv.y * w1.y + xv.z * w2.y + xv.w * w3.y;
        y2 += xv.x * w0.z + xv.y * w1.z + xv.z * w2.z + xv.w * w3.z;
        y3 += xv.x * w0.w + xv.y * w1.w + xv.z * w2.w + xv.w * w3.w;
    }
    __syncwarp();   // WAR guard before next staging round
}

// gather core: plain sum of pre-scaled features; padding -> zero row N_NODES
__device__ __forceinline__ void gcn_edge_gather(const int* __restrict__ cs,
                                                const int* __restrict__ rp,
                                                const uint2* __restrict__ x4,
                                                int node, bool valid,
                                                int gbase, int sub,
                                                float& a0, float& a1, float& a2, float& a3) {
    int k0 = 0, k1 = 0;
    if (valid) { k0 = rp[node]; k1 = rp[node + 1]; }
    int trips = (k1 - k0 + 15) >> 4;
    trips = max(trips, __shfl_xor_sync(FULL, trips, 16));
    a0 = 0.f; a1 = 0.f; a2 = 0.f; a3 = 0.f;
    for (int t = 0; t < trips; t++) {
        int k = k0 + t * 16 + sub;
        int s_l = (k < k1) ? cs[k] : N_NODES;   // zero row for padding
#pragma unroll
        for (int j = 0; j < 16; j++) {
            int s = __shfl_sync(FULL, s_l, gbase | j);
            uint2 v = x4[s * 16 + sub];
            float2 f0 = __half22float2(*(__half2*)&v.x);
            float2 f1 = __half22float2(*(__half2*)&v.y);
            a0 += f0.x; a1 += f0.y;
            a2 += f1.x; a3 += f1.y;
        }
    }
}

// ---------------- GCN layer 1: persistent, 2 nodes/warp, bufA -> bufB --------
__global__ void __launch_bounds__(256) k_gcn1(const float* __restrict__ W,
                                              const float* __restrict__ b) {
    __shared__ float4 Ws4[U * U / 4];
    __shared__ float4 bs4[U / 4];
    __shared__ __align__(16) float xstage[8][STAGE_F];
    int tid = threadIdx.x;
    for (int i = tid; i < U * U; i += blockDim.x) ((float*)Ws4)[i] = W[i];
    if (tid < U) ((float*)bs4)[tid] = b[tid];
    __syncthreads();
    int br = blockIdx.y;
    int lane = tid & 31, warp = tid >> 5;
    int sub = lane & 15, gbase = lane & 16;
    int half_off = (lane >> 4) * 68;
    float* stage = xstage[warp];
    const int*   cs = g_csrc + br * E_TOT;
    const int*   rp = g_rowptr + br * (N_NODES + 1);
    const float* dinv = g_dinv + br * N_NODES;
    const uint2* x4 = g_bufA + (size_t)br * NSTR * 16;
    uint2* outb = g_bufB + (size_t)br * NSTR * 16;
    for (int tile = blockIdx.x; tile < NTILES; tile += gridDim.x) {
        int node = (tile * 8 + warp) * 2 + (lane >> 4);
        bool valid = node < N_NODES;
        float dn = valid ? dinv[node] : 0.f;
        float a0, a1, a2, a3;
        gcn_edge_gather(cs, rp, x4, node, valid, gbase, sub, a0, a1, a2, a3);
        a0 *= dn; a1 *= dn; a2 *= dn; a3 *= dn;
        float4 bv = bs4[sub];
        float y0 = bv.x, y1 = bv.y, y2 = bv.z, y3 = bv.w;
        gemv64(Ws4, stage, half_off, sub, a0, a1, a2, a3, y0, y1, y2, y3);
        if (valid) {
            __half2 h0 = __floats2half2_rn(ftanh(y0) * dn, ftanh(y1) * dn);
            __half2 h1 = __floats2half2_rn(ftanh(y2) * dn, ftanh(y3) * dn);
            uint2 o;
            o.x = *(unsigned*)&h0; o.y = *(unsigned*)&h1;
            outb[node * 16 + sub] = o;
        }
    }
}

// ---------------- GCN layer 2 + MLP + mean-pool, persistent, 2 nodes/warp ----
__global__ void __launch_bounds__(256) k_gcn2_mlp(
                           const float* __restrict__ W, const float* __restrict__ b,
                           const int* __restrict__ ba, const int* __restrict__ bb,
                           const float* __restrict__ W1, const float* __restrict__ b1,
                           const float* __restrict__ W2, const float* __restrict__ b2,
                           const float* __restrict__ W3, const float* __restrict__ b3) {
    __shared__ float4 Ws4[U * U / 4], W1s4[U * U / 4];
    __shared__ float2 W2s2[U * 16];
    __shared__ float4 bs4[U / 4], b1s4[U / 4];
    __shared__ float  b2s[32], W3s[32], b3s;
    __shared__ __align__(16) float xstage[8][STAGE_F];
    int tid = threadIdx.x;
    for (int i = tid; i < U * U; i += blockDim.x) {
        ((float*)Ws4)[i] = W[i];
        ((float*)W1s4)[i] = W1[i];
    }
    for (int i = tid; i < U * 32; i += blockDim.x) ((float*)W2s2)[i] = W2[i];
    if (tid < U)  { ((float*)bs4)[tid] = b[tid]; ((float*)b1s4)[tid] = b1[tid]; }
    if (tid < 32) { b2s[tid] = b2[tid]; W3s[tid] = W3[tid]; }
    if (tid == 0) b3s = b3[0];
    __syncthreads();
    int br = blockIdx.y;
    int lane = tid & 31, warp = tid >> 5;
    int sub = lane & 15, gbase = lane & 16;
    int half_off = (lane >> 4) * 68;
    float* stage = xstage[warp];
    const int*   cs = g_csrc + br * E_TOT;
    const int*   rp = g_rowptr + br * (N_NODES + 1);
    const float* dinv = g_dinv + br * N_NODES;
    const uint2* x4 = g_bufB + (size_t)br * NSTR * 16;
    const int* batch = br ? bb : ba;
    for (int tile = blockIdx.x; tile < NTILES; tile += gridDim.x) {
        int node = (tile * 8 + warp) * 2 + (lane >> 4);
        bool valid = node < N_NODES;
        float dn = valid ? dinv[node] : 0.f;
        float a0, a1, a2, a3;
        gcn_edge_gather(cs, rp, x4, node, valid, gbase, sub, a0, a1, a2, a3);
        a0 *= dn; a1 *= dn; a2 *= dn; a3 *= dn;
        // GCN GEMV + tanh
        float4 bv = bs4[sub];
        float y0 = bv.x, y1 = bv.y, y2 = bv.z, y3 = bv.w;
        gemv64(Ws4, stage, half_off, sub, a0, a1, a2, a3, y0, y1, y2, y3);
        y0 = ftanh(y0); y1 = ftanh(y1); y2 = ftanh(y2); y3 = ftanh(y3);
        // MLP1 GEMV + tanh
        float4 b1v = b1s4[sub];
        float z0 = b1v.x, z1 = b1v.y, z2 = b1v.z, z3 = b1v.w;
        gemv64(W1s4, stage, half_off, sub, y0, y1, y2, y3, z0, z1, z2, z3);
        z0 = ftanh(z0); z1 = ftanh(z1); z2 = ftanh(z2); z3 = ftanh(z3);
        // MLP2 (64->32): stage z, broadcast-read per q
        *reinterpret_cast<float4*>(stage + half_off + sub * 4) =
            make_float4(z0, z1, z2, z3);
        __syncwarp();
        float p0 = b2s[2 * sub], p1 = b2s[2 * sub + 1];
        const float* zs = stage + half_off;
#pragma unroll 4
        for (int q = 0; q < 16; q++) {
            float4 zv = *reinterpret_cast<const float4*>(zs + q * 4);
            float2 w0 = W2s2[(4 * q + 0) * 16 + sub];
            float2 w1 = W2s2[(4 * q + 1) * 16 + sub];
            float2 w2 = W2s2[(4 * q + 2) * 16 + sub];
            float2 w3 = W2s2[(4 * q + 3) * 16 + sub];
            p0 += zv.x * w0.x + zv.y * w1.x + zv.z * w2.x + zv.w * w3.x;
            p1 += zv.x * w0.y + zv.y * w1.y + zv.z * w2.y + zv.w * w3.y;
        }
        __syncwarp();
        p0 = ftanh(p0); p1 = ftanh(p1);
        // MLP3 (32->1), reduce within 16-lane group
        float c = p0 * W3s[2 * sub] + p1 * W3s[2 * sub + 1];
#pragma unroll
        for (int o = 8; o > 0; o >>= 1) c += __shfl_xor_sync(FULL, c, o);
        if (valid && sub == 0) {
            int g = batch[node];
            atomicAdd(&g_psum[br * NG + g], c + b3s);
            atomicAdd(&g_pcnt[br * NG + g], 1.0f);
        }
    }
}

// ---------------- final: output + restore pool zeros for next replay --------
__global__ void k_final(float* __restrict__ out) {
    int g = blockIdx.x * blockDim.x + threadIdx.x;
    if (g >= NG) return;
    float ua = g_psum[g]      / fmaxf(g_pcnt[g], 1.f);
    float ub = g_psum[NG + g] / fmaxf(g_pcnt[NG + g], 1.f);
    out[g] = 1.f / (1.f + expf(-(ub - ua)));
    g_psum[g] = 0.f; g_psum[NG + g] = 0.f;
    g_pcnt[g] = 0.f; g_pcnt[NG + g] = 0.f;
}

// ---------------- host orchestration ----------------
extern "C" void kernel_launch(void* const* d_in, const int* in_sizes, int n_in,
                              void* d_out, int out_size) {
    const float* x_a   = (const float*)d_in[0];
    const float* x_b   = (const float*)d_in[1];
    const int*   ei_a  = (const int*)  d_in[2];
    const int*   ei_b  = (const int*)  d_in[3];
    const int*   ba    = (const int*)  d_in[4];
    const int*   bb    = (const int*)  d_in[5];
    const float* Wgat  = (const float*)d_in[6];
    const float* a_src = (const float*)d_in[7];
    const float* a_dst = (const float*)d_in[8];
    const float* bgat  = (const float*)d_in[9];
    const float* Wgcn  = (const float*)d_in[10];
    const float* bgcn  = (const float*)d_in[11];
    const float* W1    = (const float*)d_in[12];
    const float* b1    = (const float*)d_in[13];
    const float* W2    = (const float*)d_in[14];
    const float* b2    = (const float*)d_in[15];
    const float* W3    = (const float*)d_in[16];
    const float* b3    = (const float*)d_in[17];

    dim3 gD((NE4 + 255) / 256, 2);                // deg: 4 edges/thread
    dim3 gF((NE4 + N_NODES + 255) / 256, 2);      // fill: real edges + self loops
    dim3 gS(SCAN_NB, 2);
    dim3 gN((N_NODES + 255) / 256, 2);
    dim3 gW((N_NODES + 7) / 8, 2);                // GAT: 1 node/warp
    dim3 gP1(592, 2);                              // persistent GCN1
    dim3 gP2(296, 2);                              // persistent GCN2

    k_deg<<<gD, 256>>>(ei_a, ei_b, Wgat, a_src, a_dst);
    k_scan1<<<gS, SCAN_B>>>();
    k_scan3<<<gN, 256>>>(x_a, x_b);
    k_fill<<<gF, 256>>>(ei_a, ei_b);
    k_gat_gather<<<gW, 256>>>(Wgat, bgat);
    k_gcn1<<<gP1, 256>>>(Wgcn, bgcn);
    k_gcn2_mlp<<<gP2, 256>>>(Wgcn + U * U, bgcn + U, ba, bb,
                             W1, b1, W2, b2, W3, b3);
    k_final<<<2, 256>>>((float*)d_out);
}

// round 17
// speedup vs baseline: 1.5500x; 1.5500x over previous
#include <cuda_runtime.h>
#include <cuda_fp16.h>
#include <math.h>

#define N_NODES 50000
#define NSTR    (N_NODES + 1)   // feature-row stride; row N_NODES = reserved zero row
#define N_EDGES 800000
#define E_TOT   850000          // edges + self loops
#define NE4     (N_EDGES / 4)   // 200000
#define NF4     (E_TOT / 4)     // 212500 (incl. self-loop tail)
#define U       64
#define NG      512
#define F_IN    9
#define SCAN_B  1024
#define SCAN_NB ((N_NODES + SCAN_B - 1) / SCAN_B)   // 49
#define NTILES  ((N_NODES + 15) / 16)               // 3125
#define FULL    0xffffffffu

// ---------------- scratch (device globals; zero-initialized at load) --------
__device__ uint2  g_bufA[2 * NSTR * 16];      // fp16 features*dinv; row N_NODES stays 0
__device__ uint2  g_bufB[2 * NSTR * 16];
__device__ float4 g_xpack[2 * N_NODES * 2];   // 32B/node: [as_f32, x0..x8 f16, pad]
__device__ float  g_ad[2 * N_NODES];
__device__ float  g_dinv[2 * N_NODES];
__device__ int    g_deg[2 * N_NODES];         // real-edge count; re-zeroed by k_scan3
__device__ int    g_rowtmp[2 * N_NODES];
__device__ int    g_rowptr[2 * (N_NODES + 1)];
__device__ int    g_cursor[2 * N_NODES];
__device__ int    g_bsum[2 * SCAN_NB];
__device__ int    g_csrc[2 * E_TOT];          // src per CSR slot
__device__ float  g_wa[F_IN], g_wd[F_IN];
__device__ float  g_psum[2 * NG];             // re-zeroed by k_final each pass
__device__ float  g_pcnt[2 * NG];

// fast tanh: ~7 SASS inst; rel err ~1e-6
__device__ __forceinline__ float ftanh(float x) {
    float e = __expf(2.f * x);
    return 1.f - __fdividef(2.f, e + 1.f);
}

// ---------------- CSR build ----------------
// k_deg: 4 real edges/thread (self-loops folded analytically); block0 computes wa/wd
__global__ void k_deg(const int* __restrict__ ei_a, const int* __restrict__ ei_b,
                      const float* __restrict__ W, const float* __restrict__ a_src,
                      const float* __restrict__ a_dst) {
    if (blockIdx.x == 0 && blockIdx.y == 0) {
        int t = threadIdx.x;
        if (t < F_IN) {
            float s = 0.f;
            for (int c = 0; c < U; c++) s += W[t * U + c] * a_src[c];
            g_wa[t] = s;
        } else if (t >= 16 && t < 16 + F_IN) {
            int f = t - 16;
            float s = 0.f;
            for (int c = 0; c < U; c++) s += W[f * U + c] * a_dst[c];
            g_wd[f] = s;
        }
    }
    int br = blockIdx.y;
    int i = blockIdx.x * blockDim.x + threadIdx.x;
    if (i >= NE4) return;
    const int4* dst4 = reinterpret_cast<const int4*>((br ? ei_b : ei_a) + N_EDGES);
    int4 d = dst4[i];
    int* deg = g_deg + br * N_NODES;
    atomicAdd(&deg[d.x], 1);   // no return use -> REDG fire-and-forget
    atomicAdd(&deg[d.y], 1);
    atomicAdd(&deg[d.z], 1);
    atomicAdd(&deg[d.w], 1);
}
__global__ void k_scan1() {
    __shared__ int sm[SCAN_B];
    int br = blockIdx.y;
    int t = threadIdx.x;
    int i = blockIdx.x * SCAN_B + t;
    int v = (i < N_NODES) ? (g_deg[br * N_NODES + i] + 1) : 0;   // +1 self loop
    sm[t] = v;
    __syncthreads();
#pragma unroll
    for (int off = 1; off < SCAN_B; off <<= 1) {
        int add = (t >= off) ? sm[t - off] : 0;
        __syncthreads();
        sm[t] += add;
        __syncthreads();
    }
    if (i < N_NODES) g_rowtmp[br * N_NODES + i] = sm[t];
    if (t == SCAN_B - 1) g_bsum[br * SCAN_NB + blockIdx.x] = sm[t];
}
// scan3: finalize CSR + dinv + 32B packed [as_f32, x f16]; re-zero deg
__global__ void k_scan3(const float* __restrict__ xa, const float* __restrict__ xb) {
    __shared__ int bsm[SCAN_NB];
    int br = blockIdx.y;
    int t = threadIdx.x;
    if (t < SCAN_NB) bsm[t] = g_bsum[br * SCAN_NB + t];
    __syncthreads();
    int i = blockIdx.x * blockDim.x + t;
    if (i >= N_NODES) return;
    int blk = i / SCAN_B;
    int pre = 0;
    for (int b = 0; b < blk; b++) pre += bsm[b];
    int incl = g_rowtmp[br * N_NODES + i] + pre;
    int d = g_deg[br * N_NODES + i] + 1;       // + self loop
    g_deg[br * N_NODES + i] = 0;               // restore zero for next replay
    g_rowptr[br * (N_NODES + 1) + i + 1] = incl;
    g_cursor[br * N_NODES + i] = incl - d;
    g_dinv[br * N_NODES + i] = rsqrtf((float)d);
    if (i == 0) g_rowptr[br * (N_NODES + 1)] = 0;
    const float* x = br ? xb : xa;
    const float* xi = x + i * F_IN;
    float v[F_IN];
    float as = 0.f, ad = 0.f;
#pragma unroll
    for (int f = 0; f < F_IN; f++) {
        v[f] = xi[f];
        as += v[f] * g_wa[f];
        ad += v[f] * g_wd[f];
    }
    g_ad[br * N_NODES + i] = ad;
    __half2 h01 = __floats2half2_rn(v[0], v[1]);
    __half2 h23 = __floats2half2_rn(v[2], v[3]);
    __half2 h45 = __floats2half2_rn(v[4], v[5]);
    __half2 h67 = __floats2half2_rn(v[6], v[7]);
    __half2 h8z = __floats2half2_rn(v[8], 0.f);
    float4* xp = g_xpack + ((size_t)br * N_NODES + i) * 2;
    float4 q0, q1;
    q0.x = as;
    q0.y = __uint_as_float(*(unsigned*)&h01);
    q0.z = __uint_as_float(*(unsigned*)&h23);
    q0.w = __uint_as_float(*(unsigned*)&h45);
    q1.x = __uint_as_float(*(unsigned*)&h67);
    q1.y = __uint_as_float(*(unsigned*)&h8z);
    q1.z = 0.f; q1.w = 0.f;
    xp[0] = q0;
    xp[1] = q1;
}
// fill: 4 edges/thread; tail range covers self loops
__global__ void k_fill(const int* __restrict__ ei_a, const int* __restrict__ ei_b) {
    int br = blockIdx.y;
    int i = blockIdx.x * blockDim.x + threadIdx.x;
    if (i >= NF4) return;
    int* cur = g_cursor + br * N_NODES;
    int* cs  = g_csrc + br * E_TOT;
    if (i < NE4) {
        const int* ei = br ? ei_b : ei_a;
        int4 s = reinterpret_cast<const int4*>(ei)[i];
        int4 d = reinterpret_cast<const int4*>(ei + N_EDGES)[i];
        int p0 = atomicAdd(&cur[d.x], 1);
        int p1 = atomicAdd(&cur[d.y], 1);
        int p2 = atomicAdd(&cur[d.z], 1);
        int p3 = atomicAdd(&cur[d.w], 1);
        cs[p0] = s.x; cs[p1] = s.y; cs[p2] = s.z; cs[p3] = s.w;
    } else {
        int base = (i - NE4) * 4;
#pragma unroll
        for (int j = 0; j < 4; j++) {
            int n = base + j;
            int p = atomicAdd(&cur[n], 1);
            cs[p] = n;
        }
    }
}

// ---------------- GAT: softmax aggregate of 32B packed x, then @W -----------
__global__ void k_gat_gather(const float* __restrict__ W, const float* __restrict__ b) {
    __shared__ float Ws[F_IN * U];
    __shared__ float bs[U];
    int tid = threadIdx.x;
    for (int i = tid; i < F_IN * U; i += blockDim.x) Ws[i] = W[i];
    if (tid < U) bs[tid] = b[tid];
    __syncthreads();
    int br = blockIdx.y;
    int lane = tid & 31;
    int node = blockIdx.x * (blockDim.x >> 5) + (tid >> 5);
    if (node >= N_NODES) return;
    const int*    cs = g_csrc + br * E_TOT;
    const int*    rp = g_rowptr + br * (N_NODES + 1);
    const float4* xp = g_xpack + (size_t)br * N_NODES * 2;
    int k0 = rp[node], k1 = rp[node + 1];
    float ad_n = g_ad[br * N_NODES + node];
    float acc[F_IN] = {0, 0, 0, 0, 0, 0, 0, 0, 0};
    float ssum = 0.f;
    for (int k = k0 + lane; k < k1; k += 32) {
        int s = cs[k];
        float4 q0 = xp[s * 2];
        float4 q1 = xp[s * 2 + 1];
        float e = q0.x + ad_n;
        e = e > 0.f ? e : 0.2f * e;
        e = fminf(e, 80.f);
        float ex = __expf(e);
        ssum += ex;
        unsigned u01 = __float_as_uint(q0.y), u23 = __float_as_uint(q0.z);
        unsigned u45 = __float_as_uint(q0.w), u67 = __float_as_uint(q1.x);
        unsigned u8z = __float_as_uint(q1.y);
        float2 x01 = __half22float2(*(__half2*)&u01);
        float2 x23 = __half22float2(*(__half2*)&u23);
        float2 x45 = __half22float2(*(__half2*)&u45);
        float2 x67 = __half22float2(*(__half2*)&u67);
        float2 x8z = __half22float2(*(__half2*)&u8z);
        acc[0] += ex * x01.x; acc[1] += ex * x01.y;
        acc[2] += ex * x23.x; acc[3] += ex * x23.y;
        acc[4] += ex * x45.x; acc[5] += ex * x45.y;
        acc[6] += ex * x67.x; acc[7] += ex * x67.y;
        acc[8] += ex * x8z.x;
    }
#pragma unroll
    for (int o = 16; o > 0; o >>= 1) {
        ssum += __shfl_xor_sync(FULL, ssum, o);
#pragma unroll
        for (int f = 0; f < F_IN; f++) acc[f] += __shfl_xor_sync(FULL, acc[f], o);
    }
    float inv = 1.f / ssum;
    int c0 = 2 * lane;
    float y0 = bs[c0], y1 = bs[c0 + 1];
#pragma unroll
    for (int f = 0; f < F_IN; f++) {
        float v = acc[f] * inv;
        y0 += v * Ws[f * U + c0];
        y1 += v * Ws[f * U + c0 + 1];
    }
    float dn = g_dinv[br * N_NODES + node];   // pre-scale for GCN1's gather
    __half2* out2 = reinterpret_cast<__half2*>(g_bufA) + ((size_t)br * NSTR + node) * 32;
    out2[lane] = __floats2half2_rn(ftanh(y0) * dn, ftanh(y1) * dn);
}

// GEMV via smem-broadcast x (16B-aligned stage; offsets 0/68 floats bank-free)
#define STAGE_F 136
__device__ __forceinline__ void gemv64(const float4* __restrict__ Wsm,
                                       float* stage, int half_off, int sub,
                                       float v0, float v1, float v2, float v3,
                                       float& y0, float& y1, float& y2, float& y3) {
    *reinterpret_cast<float4*>(stage + half_off + sub * 4) = make_float4(v0, v1, v2, v3);
    __syncwarp();
    const float* xs = stage + half_off;
#pragma unroll 4
    for (int q = 0; q < 16; q++) {
        float4 xv = *reinterpret_cast<const float4*>(xs + q * 4);
        float4 w0 = Wsm[(4 * q + 0) * 16 + sub];
        float4 w1 = Wsm[(4 * q + 1) * 16 + sub];
        float4 w2 = Wsm[(4 * q + 2) * 16 + sub];
        float4 w3 = Wsm[(4 * q + 3) * 16 + sub];
        y0 += xv.x * w0.x + xv.y * w1.x + xv.z * w2.x + xv.w * w3.x;
        y1 += xv.x * w0.y + xv.y * w1.y + xv.z * w2.y + xv.w * w3.y;
        y2 += xv.x * w0.z + xv.y * w1.z + xv.z * w2.z + xv.w * w3.z;
        y3 += xv.x * w0.w + xv.y * w1.w + xv.z * w2.w + xv.w * w3.w;
    }
    __syncwarp();   // WAR guard before next staging round
}

// gather core: plain sum of pre-scaled features; padding -> zero row N_NODES
__device__ __forceinline__ void gcn_edge_gather(const int* __restrict__ cs,
                                                const int* __restrict__ rp,
                                                const uint2* __restrict__ x4,
                                                int node, bool valid,
                                                int gbase, int sub,
                                                float& a0, float& a1, float& a2, float& a3) {
    int k0 = 0, k1 = 0;
    if (valid) { k0 = rp[node]; k1 = rp[node + 1]; }
    int trips = (k1 - k0 + 15) >> 4;
    trips = max(trips, __shfl_xor_sync(FULL, trips, 16));
    a0 = 0.f; a1 = 0.f; a2 = 0.f; a3 = 0.f;
    for (int t = 0; t < trips; t++) {
        int k = k0 + t * 16 + sub;
        int s_l = (k < k1) ? cs[k] : N_NODES;   // zero row for padding
#pragma unroll
        for (int j = 0; j < 16; j++) {
            int s = __shfl_sync(FULL, s_l, gbase | j);
            uint2 v = x4[s * 16 + sub];
            float2 f0 = __half22float2(*(__half2*)&v.x);
            float2 f1 = __half22float2(*(__half2*)&v.y);
            a0 += f0.x; a1 += f0.y;
            a2 += f1.x; a3 += f1.y;
        }
    }
}

// ---------------- GCN layer 1: persistent, 2 nodes/warp, bufA -> bufB --------
__global__ void __launch_bounds__(256) k_gcn1(const float* __restrict__ W,
                                              const float* __restrict__ b) {
    __shared__ float4 Ws4[U * U / 4];
    __shared__ float4 bs4[U / 4];
    __shared__ __align__(16) float xstage[8][STAGE_F];
    int tid = threadIdx.x;
    for (int i = tid; i < U * U; i += blockDim.x) ((float*)Ws4)[i] = W[i];
    if (tid < U) ((float*)bs4)[tid] = b[tid];
    __syncthreads();
    int br = blockIdx.y;
    int lane = tid & 31, warp = tid >> 5;
    int sub = lane & 15, gbase = lane & 16;
    int half_off = (lane >> 4) * 68;
    float* stage = xstage[warp];
    const int*   cs = g_csrc + br * E_TOT;
    const int*   rp = g_rowptr + br * (N_NODES + 1);
    const float* dinv = g_dinv + br * N_NODES;
    const uint2* x4 = g_bufA + (size_t)br * NSTR * 16;
    uint2* outb = g_bufB + (size_t)br * NSTR * 16;
    for (int tile = blockIdx.x; tile < NTILES; tile += gridDim.x) {
        int node = (tile * 8 + warp) * 2 + (lane >> 4);
        bool valid = node < N_NODES;
        float dn = valid ? dinv[node] : 0.f;
        float a0, a1, a2, a3;
        gcn_edge_gather(cs, rp, x4, node, valid, gbase, sub, a0, a1, a2, a3);
        a0 *= dn; a1 *= dn; a2 *= dn; a3 *= dn;
        float4 bv = bs4[sub];
        float y0 = bv.x, y1 = bv.y, y2 = bv.z, y3 = bv.w;
        gemv64(Ws4, stage, half_off, sub, a0, a1, a2, a3, y0, y1, y2, y3);
        if (valid) {
            __half2 h0 = __floats2half2_rn(ftanh(y0) * dn, ftanh(y1) * dn);
            __half2 h1 = __floats2half2_rn(ftanh(y2) * dn, ftanh(y3) * dn);
            uint2 o;
            o.x = *(unsigned*)&h0; o.y = *(unsigned*)&h1;
            outb[node * 16 + sub] = o;
        }
    }
}

// ---------------- GCN layer 2 + MLP + mean-pool, persistent, 2 nodes/warp ----
__global__ void __launch_bounds__(256) k_gcn2_mlp(
                           const float* __restrict__ W, const float* __restrict__ b,
                           const int* __restrict__ ba, const int* __restrict__ bb,
                           const float* __restrict__ W1, const float* __restrict__ b1,
                           const float* __restrict__ W2, const float* __restrict__ b2,
                           const float* __restrict__ W3, const float* __restrict__ b3) {
    __shared__ float4 Ws4[U * U / 4], W1s4[U * U / 4];
    __shared__ float2 W2s2[U * 16];
    __shared__ float4 bs4[U / 4], b1s4[U / 4];
    __shared__ float  b2s[32], W3s[32], b3s;
    __shared__ __align__(16) float xstage[8][STAGE_F];
    int tid = threadIdx.x;
    for (int i = tid; i < U * U; i += blockDim.x) {
        ((float*)Ws4)[i] = W[i];
        ((float*)W1s4)[i] = W1[i];
    }
    for (int i = tid; i < U * 32; i += blockDim.x) ((float*)W2s2)[i] = W2[i];
    if (tid < U)  { ((float*)bs4)[tid] = b[tid]; ((float*)b1s4)[tid] = b1[tid]; }
    if (tid < 32) { b2s[tid] = b2[tid]; W3s[tid] = W3[tid]; }
    if (tid == 0) b3s = b3[0];
    __syncthreads();
    int br = blockIdx.y;
    int lane = tid & 31, warp = tid >> 5;
    int sub = lane & 15, gbase = lane & 16;
    int half_off = (lane >> 4) * 68;
    float* stage = xstage[warp];
    const int*   cs = g_csrc + br * E_TOT;
    const int*   rp = g_rowptr + br * (N_NODES + 1);
    const float* dinv = g_dinv + br * N_NODES;
    const uint2* x4 = g_bufB + (size_t)br * NSTR * 16;
    const int* batch = br ? bb : ba;
    for (int tile = blockIdx.x; tile < NTILES; tile += gridDim.x) {
        int node = (tile * 8 + warp) * 2 + (lane >> 4);
        bool valid = node < N_NODES;
        float dn = valid ? dinv[node] : 0.f;
        float a0, a1, a2, a3;
        gcn_edge_gather(cs, rp, x4, node, valid, gbase, sub, a0, a1, a2, a3);
        a0 *= dn; a1 *= dn; a2 *= dn; a3 *= dn;
        // GCN GEMV + tanh
        float4 bv = bs4[sub];
        float y0 = bv.x, y1 = bv.y, y2 = bv.z, y3 = bv.w;
        gemv64(Ws4, stage, half_off, sub, a0, a1, a2, a3, y0, y1, y2, y3);
        y0 = ftanh(y0); y1 = ftanh(y1); y2 = ftanh(y2); y3 = ftanh(y3);
        // MLP1 GEMV + tanh
        float4 b1v = b1s4[sub];
        float z0 = b1v.x, z1 = b1v.y, z2 = b1v.z, z3 = b1v.w;
        gemv64(W1s4, stage, half_off, sub, y0, y1, y2, y3, z0, z1, z2, z3);
        z0 = ftanh(z0); z1 = ftanh(z1); z2 = ftanh(z2); z3 = ftanh(z3);
        // MLP2 (64->32): stage z, broadcast-read per q
        *reinterpret_cast<float4*>(stage + half_off + sub * 4) =
            make_float4(z0, z1, z2, z3);
        __syncwarp();
        float p0 = b2s[2 * sub], p1 = b2s[2 * sub + 1];
        const float* zs = stage + half_off;
#pragma unroll 4
        for (int q = 0; q < 16; q++) {
            float4 zv = *reinterpret_cast<const float4*>(zs + q * 4);
            float2 w0 = W2s2[(4 * q + 0) * 16 + sub];
            float2 w1 = W2s2[(4 * q + 1) * 16 + sub];
            float2 w2 = W2s2[(4 * q + 2) * 16 + sub];
            float2 w3 = W2s2[(4 * q + 3) * 16 + sub];
            p0 += zv.x * w0.x + zv.y * w1.x + zv.z * w2.x + zv.w * w3.x;
            p1 += zv.x * w0.y + zv.y * w1.y + zv.z * w2.y + zv.w * w3.y;
        }
        __syncwarp();
        p0 = ftanh(p0); p1 = ftanh(p1);
        // MLP3 (32->1), reduce within 16-lane group
        float c = p0 * W3s[2 * sub] + p1 * W3s[2 * sub + 1];
#pragma unroll
        for (int o = 8; o > 0; o >>= 1) c += __shfl_xor_sync(FULL, c, o);
        if (valid && sub == 0) {
            int g = batch[node];
            atomicAdd(&g_psum[br * NG + g], c + b3s);
            atomicAdd(&g_pcnt[br * NG + g], 1.0f);
        }
    }
}

// ---------------- final: output + restore pool zeros for next replay --------
__global__ void k_final(float* __restrict__ out) {
    int g = blockIdx.x * blockDim.x + threadIdx.x;
    if (g >= NG) return;
    float ua = g_psum[g]      / fmaxf(g_pcnt[g], 1.f);
    float ub = g_psum[NG + g] / fmaxf(g_pcnt[NG + g], 1.f);
    out[g] = 1.f / (1.f + expf(-(ub - ua)));
    g_psum[g] = 0.f; g_psum[NG + g] = 0.f;
    g_pcnt[g] = 0.f; g_pcnt[NG + g] = 0.f;
}

// ---------------- host orchestration ----------------
extern "C" void kernel_launch(void* const* d_in, const int* in_sizes, int n_in,
                              void* d_out, int out_size) {
    const float* x_a   = (const float*)d_in[0];
    const float* x_b   = (const float*)d_in[1];
    const int*   ei_a  = (const int*)  d_in[2];
    const int*   ei_b  = (const int*)  d_in[3];
    const int*   ba    = (const int*)  d_in[4];
    const int*   bb    = (const int*)  d_in[5];
    const float* Wgat  = (const float*)d_in[6];
    const float* a_src = (const float*)d_in[7];
    const float* a_dst = (const float*)d_in[8];
    const float* bgat  = (const float*)d_in[9];
    const float* Wgcn  = (const float*)d_in[10];
    const float* bgcn  = (const float*)d_in[11];
    const float* W1    = (const float*)d_in[12];
    const float* b1    = (const float*)d_in[13];
    const float* W2    = (const float*)d_in[14];
    const float* b2    = (const float*)d_in[15];
    const float* W3    = (const float*)d_in[16];
    const float* b3    = (const float*)d_in[17];

    dim3 gD((NE4 + 255) / 256, 2);       // deg: 4 edges/thread
    dim3 gF((NF4 + 255) / 256, 2);       // fill: 4 edges/thread incl. self loops
    dim3 gS(SCAN_NB, 2);
    dim3 gN((N_NODES + 255) / 256, 2);
    dim3 gW((N_NODES + 7) / 8, 2);       // GAT: 1 node/warp
    dim3 gP1(592, 2);                     // persistent GCN1 (8 blocks/SM)
    dim3 gP2(296, 2);                     // persistent GCN2 (4 blocks/SM by smem)

    k_deg<<<gD, 256>>>(ei_a, ei_b, Wgat, a_src, a_dst);
    k_scan1<<<gS, SCAN_B>>>();
    k_scan3<<<gN, 256>>>(x_a, x_b);
    k_fill<<<gF, 256>>>(ei_a, ei_b);
    k_gat_gather<<<gW, 256>>>(Wgat, bgat);
    k_gcn1<<<gP1, 256>>>(Wgcn, bgcn);
    k_gcn2_mlp<<<gP2, 256>>>(Wgcn + U * U, bgcn + U, ba, bb,
                             W1, b1, W2, b2, W3, b3);
    k_final<<<2, 256>>>((float*)d_out);
}